// round 5
// baseline (speedup 1.0000x reference)
#include <cuda_runtime.h>
#include <math_constants.h>
#include <cstdint>

// DetectPeaksTM: per-row sliding max (K=301) NMS + top-2 (value, index).
// Candidate-based: a survivor must equal the max of its aligned 128-tile
// (tile fully inside the +-150 window). Hot loop computes each tile's max
// value AND argmax (via REDUX + ballot). Selection verifies candidates
// best-first using tile-max bounds from smem (gmem only for rare edge cases).

#define NT    8192
#define HALF  150
#define WIN   301

typedef unsigned long long u64;
typedef unsigned int u32;

__device__ __forceinline__ u64 umax64(u64 a, u64 b) { return a > b ? a : b; }

__device__ __forceinline__ u64 shfl_xor_u64(u64 v, int d) {
    u32 lo = (u32)v, hi = (u32)(v >> 32);
    lo = __shfl_xor_sync(0xffffffffu, lo, d);
    hi = __shfl_xor_sync(0xffffffffu, hi, d);
    return ((u64)hi << 32) | lo;
}

__device__ __forceinline__ u32 absbits(float f) {
    return __float_as_uint(f) & 0x7fffffffu;
}

__global__ void __launch_bounds__(512)
detect_peaks_kernel(const float* __restrict__ x, float* __restrict__ out, int nrows) {
    __shared__ u32 tileMax[64];
    __shared__ u32 tileInfo[64];   // idx1 (13 bits) | dup<<15

    const int row  = blockIdx.x;
    const int tid  = threadIdx.x;
    const int lane = tid & 31;
    const int warp = tid >> 5;
    const u32 FULL = 0xffffffffu;

    const float* xr = x + (size_t)row * NT;
    const float4* src = (const float4*)xr;

    // ---- hot loop: per-128-tile max value + argmax ----
    float4 v[4];
#pragma unroll
    for (int k = 0; k < 4; k++) v[k] = src[tid + 512 * k];

#pragma unroll
    for (int k = 0; k < 4; k++) {
        u32 a = absbits(v[k].x), b = absbits(v[k].y);
        u32 c = absbits(v[k].z), d = absbits(v[k].w);
        u32 l1 = max(max(a, b), max(c, d));
        u32 m1 = __reduce_max_sync(FULL, l1);

        u32 em = (u32)(a == m1) | ((u32)(b == m1) << 1) |
                 ((u32)(c == m1) << 2) | ((u32)(d == m1) << 3);
        u32 bal = __ballot_sync(FULL, em != 0);
        int lf = __ffs(bal) - 1;
        u32 pk = __shfl_sync(FULL, em, lf);
        int j1 = __ffs(pk) - 1;
        bool dup = (__popc(bal) > 1) || (__popc(pk) > 1);

        int tile = warp + 16 * k;              // 0..63
        if (lane == 0) {
            tileMax[tile]  = m1;
            tileInfo[tile] = (u32)(tile * 128 + lf * 4 + j1) | (dup ? 0x8000u : 0u);
        }
    }
    __syncthreads();

    if (warp != 0) return;

    // ---- build candidate keys: (val << 32) | ~idx  (val desc, idx asc) ----
    u64 keys[2], kd[2] = {0ull, 0ull};
    bool dupf[2];
#pragma unroll
    for (int q = 0; q < 2; q++) {
        int t = lane + 32 * q;
        u32 m1 = tileMax[t];
        u32 info = tileInfo[t];
        u32 idx = info & 0x3fffu;
        dupf[q] = (info & 0x8000u) != 0;
        keys[q] = ((u64)m1 << 32) | (u32)(~idx);
    }

    // ---- rare: recover 2nd occurrence index for duplicate-max tiles ----
#pragma unroll
    for (int q = 0; q < 2; q++) {
        u32 db = __ballot_sync(FULL, dupf[q]);
        while (db) {
            int l = __ffs(db) - 1; db &= db - 1;
            int t = l + 32 * q;
            u32 m1 = tileMax[t];
            float4 tv = ((const float4*)(xr + t * 128))[lane];
            u32 em = (u32)(absbits(tv.x) == m1) | ((u32)(absbits(tv.y) == m1) << 1) |
                     ((u32)(absbits(tv.z) == m1) << 2) | ((u32)(absbits(tv.w) == m1) << 3);
            u32 b2 = __ballot_sync(FULL, em != 0);
            int lf = __ffs(b2) - 1;
            u32 pk = __shfl_sync(FULL, em, lf);
            int idx2;
            if (__popc(pk) > 1) {
                idx2 = t * 128 + lf * 4 + (__ffs(pk & (pk - 1)) - 1);
            } else {
                u32 b3 = b2 & (b2 - 1);
                int ls = __ffs(b3) - 1;
                u32 pk2 = __shfl_sync(FULL, em, ls);
                idx2 = t * 128 + ls * 4 + (__ffs(pk2) - 1);
            }
            if (lane == l) kd[q] = ((u64)m1 << 32) | (u32)(~(u32)idx2);
        }
    }

    // ---- selection: best-first with tile-max bound verification ----
    float rv0 = 0.0f, rv1 = 0.0f;
    int   ri0 = 0,    ri1 = 0;
    int found = 0;

    for (int it = 0; it < 128 && found < 2; it++) {
        u64 best = umax64(umax64(keys[0], keys[1]), umax64(kd[0], kd[1]));
#pragma unroll
        for (int s = 16; s > 0; s >>= 1) best = umax64(best, shfl_xor_u64(best, s));
        if (best == 0ull) break;
        if (keys[0] == best) keys[0] = 0;
        if (keys[1] == best) keys[1] = 0;
        if (kd[0]   == best) kd[0]   = 0;
        if (kd[1]   == best) kd[1]   = 0;

        u32 val = (u32)(best >> 32);
        int idx = (int)(~(u32)(best & 0xffffffffull));

        int lo = max(idx - HALF, 0);
        int hi = min(idx + HALF, NT - 1);
        int ta = lo >> 7, tb = hi >> 7;

        // bound over touched tiles (<=4), from smem
        int t = ta + lane;
        u32 tm = (t <= tb) ? tileMax[t] : 0u;
        u32 bound = __reduce_max_sync(FULL, tm);

        bool accept = (bound <= val);
        if (!accept) {
            // strictly-interior tile exceeding val -> exact reject
            bool fullt = (t <= tb) && (t * 128 >= lo) && (t * 128 + 127 <= hi);
            u32 tmf = fullt ? tm : 0u;
            if (__reduce_max_sync(FULL, tmf) > val) continue;

            // ambiguous edges: exact window max from gmem (rare)
            u32 mb = 0;
            int base = idx - HALF;
#pragma unroll
            for (int r = 0; r < 10; r++) {
                int off = lane + 32 * r;
                int p = min(max(base + off, 0), NT - 1);
                u32 xb = absbits(__ldg(xr + p));
                if (off < WIN) mb = max(mb, xb);
            }
            mb = __reduce_max_sync(FULL, mb);
            if (mb > val) continue;
            accept = true;
        }

        if (found == 0) { rv0 = __uint_as_float(val); ri0 = idx; }
        else            { rv1 = __uint_as_float(val); ri1 = idx; }
        found++;
    }

    if (lane == 0) {
        if (found < 2) {                 // <2 survivors: next score is 0
            rv1 = 0.0f;
            ri1 = (found >= 1 && ri0 == 0) ? 1 : 0;
        }
        out[row * 2 + 0] = rv0;
        out[row * 2 + 1] = rv1;
        out[(size_t)nrows * 2 + row * 2 + 0] = (float)ri0;
        out[(size_t)nrows * 2 + row * 2 + 1] = (float)ri1;
    }
}

extern "C" void kernel_launch(void* const* d_in, const int* in_sizes, int n_in,
                              void* d_out, int out_size) {
    const float* x = (const float*)d_in[0];
    float* out = (float*)d_out;
    int nrows = in_sizes[0] / NT;   // 6144
    detect_peaks_kernel<<<nrows, 512>>>(x, out, nrows);
}

// round 6
// speedup vs baseline: 1.0211x; 1.0211x over previous
#include <cuda_runtime.h>
#include <cstdint>

// DetectPeaksTM: per-row sliding max (K=301) NMS + top-2 (value, index).
// Candidate-based: a survivor must equal the max of its aligned 128-tile
// (tile fully inside the +-150 window). Hot loop computes ONLY each tile's
// max abs value (3 FMNMX + REDUX per 16B/thread). Indices are recovered
// lazily by rescanning the (L1-hot) winning tile during selection.

#define NT    8192
#define HALF  150
#define WIN   301

typedef unsigned long long u64;
typedef unsigned int u32;

__device__ __forceinline__ u32 absbits(float f) {
    return __float_as_uint(f) & 0x7fffffffu;
}
__device__ __forceinline__ u64 umax64(u64 a, u64 b) { return a > b ? a : b; }
__device__ __forceinline__ u64 shfl_xor_u64(u64 v, int d) {
    u32 lo = (u32)v, hi = (u32)(v >> 32);
    lo = __shfl_xor_sync(0xffffffffu, lo, d);
    hi = __shfl_xor_sync(0xffffffffu, hi, d);
    return ((u64)hi << 32) | lo;
}

// First index > bound inside tile whose absbits == val, or -1.
// em: per-lane 4-bit match mask for the tile's float4 at this lane.
__device__ __forceinline__ int find_next(u32 em, int tile, int bound, int lane) {
    int base = tile * 128 + lane * 4;
    int rel = bound - base;                  // element j excluded iff j <= rel
    u32 emm = em;
    if (rel >= 3) emm = 0;
    else if (rel >= 0) emm &= (0xFu << (rel + 1));
    u32 bl = __ballot_sync(0xffffffffu, emm != 0);
    if (!bl) return -1;
    int lf = __ffs((int)bl) - 1;
    u32 pk = __shfl_sync(0xffffffffu, emm, lf);
    return tile * 128 + lf * 4 + (__ffs((int)pk) - 1);
}

__global__ void __launch_bounds__(512)
detect_peaks_kernel(const float* __restrict__ x, float* __restrict__ out, int nrows) {
    __shared__ u32 tileMax[64];

    const int row  = blockIdx.x;
    const int tid  = threadIdx.x;
    const int lane = tid & 31;
    const int warp = tid >> 5;
    const u32 FULL = 0xffffffffu;

    const float* xr = x + (size_t)row * NT;
    const float4* src = (const float4*)xr;

    // ---- hot loop: per-128-tile max of |x| (values only) ----
    float4 v[4];
#pragma unroll
    for (int k = 0; k < 4; k++) v[k] = src[tid + 512 * k];

#pragma unroll
    for (int k = 0; k < 4; k++) {
        float m01 = fmaxf(fabsf(v[k].x), fabsf(v[k].y));
        float m23 = fmaxf(fabsf(v[k].z), fabsf(v[k].w));
        float m   = fmaxf(m01, m23);
        u32 m1 = __reduce_max_sync(FULL, __float_as_uint(m));
        if (lane == 0) tileMax[warp + 16 * k] = m1;
    }
    __syncthreads();

    if (warp != 0) return;

    // ---- selection (warp 0): best-first over tile maxima ----
    // key = (val << 32) | ~(index lower bound); unique, orders (val desc, idx asc)
    u64 keys[2];
#pragma unroll
    for (int q = 0; q < 2; q++) {
        int t = lane + 32 * q;
        keys[q] = ((u64)tileMax[t] << 32) | (u32)(~(u32)(t * 128));
    }
    u64 pend = 0;        // at most one pending same-value occurrence (uniform)
    int pendIdx = -1;

    float rv0 = 0.0f, rv1 = 0.0f;
    int   ri0 = 0,    ri1 = 0;
    int found = 0;

    for (int it = 0; it < 192 && found < 2; it++) {
        u64 best = umax64(umax64(keys[0], keys[1]), pend);
#pragma unroll
        for (int s = 16; s > 0; s >>= 1) best = umax64(best, shfl_xor_u64(best, s));
        if (best == 0ull) break;

        bool wasPend = (best == pend && pend != 0ull);
        if (wasPend) pend = 0;
        if (keys[0] == best) keys[0] = 0;
        if (keys[1] == best) keys[1] = 0;

        u32 val = (u32)(best >> 32);
        int tile, idxV;
        if (wasPend) { idxV = pendIdx; tile = idxV >> 7; }
        else         { tile = (int)((~(u32)(best & 0xffffffffull)) >> 7); idxV = -1; }

        // rescan tile (L1-hot) for occurrence chain
        float4 tv = ((const float4*)(xr + tile * 128))[lane];
        u32 em = (u32)(absbits(tv.x) == val)        |
                 ((u32)(absbits(tv.y) == val) << 1) |
                 ((u32)(absbits(tv.z) == val) << 2) |
                 ((u32)(absbits(tv.w) == val) << 3);
        if (!wasPend) idxV = find_next(em, tile, tile * 128 - 1, lane);
        int nxt = find_next(em, tile, idxV, lane);
        if (nxt >= 0) { pend = ((u64)val << 32) | (u32)(~(u32)nxt); pendIdx = nxt; }

        // verify idxV against window max using tile bounds (smem)
        int lo = max(idxV - HALF, 0);
        int hi = min(idxV + HALF, NT - 1);
        int ta = lo >> 7, tb = hi >> 7;
        int t = ta + lane;
        u32 tm = (t <= tb) ? tileMax[t] : 0u;
        u32 bound = __reduce_max_sync(FULL, tm);

        bool accept = (bound <= val);
        if (!accept) {
            bool fullt = (t <= tb) && (t * 128 >= lo) && (t * 128 + 127 <= hi);
            if (__reduce_max_sync(FULL, fullt ? tm : 0u) > val) continue;
            // ambiguous edge tiles: exact window max from gmem (rare)
            u32 mb = 0;
            int base = idxV - HALF;
#pragma unroll
            for (int r = 0; r < 10; r++) {
                int off = lane + 32 * r;
                int p = min(max(base + off, 0), NT - 1);
                u32 xb = absbits(__ldg(xr + p));
                if (off < WIN) mb = max(mb, xb);
            }
            if (__reduce_max_sync(FULL, mb) > val) continue;
            accept = true;
        }

        if (found == 0) { rv0 = __uint_as_float(val); ri0 = idxV; }
        else            { rv1 = __uint_as_float(val); ri1 = idxV; }
        found++;
    }

    if (lane == 0) {
        if (found < 2) {                 // <2 survivors: next-best score is 0
            rv1 = 0.0f;
            ri1 = (found >= 1 && ri0 == 0) ? 1 : 0;
        }
        out[row * 2 + 0] = rv0;
        out[row * 2 + 1] = rv1;
        out[(size_t)nrows * 2 + row * 2 + 0] = (float)ri0;
        out[(size_t)nrows * 2 + row * 2 + 1] = (float)ri1;
    }
}

extern "C" void kernel_launch(void* const* d_in, const int* in_sizes, int n_in,
                              void* d_out, int out_size) {
    const float* x = (const float*)d_in[0];
    float* out = (float*)d_out;
    int nrows = in_sizes[0] / NT;   // 6144
    detect_peaks_kernel<<<nrows, 512>>>(x, out, nrows);
}